// round 9
// baseline (speedup 1.0000x reference)
#include <cuda_runtime.h>
#include <math.h>
#include <stdint.h>

// ---------------- problem constants ----------------
#define BATCHN  2
#define EDIM    768
#define LTOK    1024
#define BWIN    8
#define NHEADS  8
#define HDIM    96
#define OUT_ELEMS (BATCHN*EDIM*64*64)

// ---------------- scratch ----------------
__device__ float g_rx [BATCHN*3*1024*1024];
__device__ float g_rp [BWIN*LTOK*EDIM];
__device__ float g_opn[BWIN*LTOK*EDIM];
__device__ float g_rpn[BWIN*LTOK*EDIM];
__device__ float g_q  [BWIN*LTOK*EDIM];
__device__ float g_bv [BWIN*LTOK*EDIM];
__device__ float g_avt[BATCHN*4096*EDIM];
__device__ float g_bvt[BWIN*NHEADS*HDIM*LTOK];
__device__ float g_pet[4096*EDIM];
__device__ float g_inq[BWIN*NHEADS*LTOK];
__device__ float g_inb[BWIN*NHEADS*LTOK];
__device__ float g_G  [64];
// tf32-pre-rounded weights
__device__ float g_wq[EDIM*EDIM];
__device__ float g_wb[EDIM*EDIM];
__device__ float g_wp[EDIM*EDIM];
__device__ float g_wr[768*256];
__device__ float g_wo[64*768];     // origin conv weights transposed [i][oc], fp32

__device__ __forceinline__ uint32_t f2tf32(float f) {
    uint32_t u;
    asm("cvt.rna.tf32.f32 %0, %1;" : "=r"(u) : "f"(f));
    return u;
}
__device__ __forceinline__ float rtf(float f) { return __uint_as_float(f2tf32(f)); }
__device__ __forceinline__ float4 cvt4(float4 v) {
    v.x = rtf(v.x); v.y = rtf(v.y); v.z = rtf(v.z); v.w = rtf(v.w);
    return v;
}

// ---------------- weight pre-rounding + origin-weight transpose ----------------
__global__ void k_cvtw(const float* __restrict__ qw, const float* __restrict__ bw,
                       const float* __restrict__ pw, const float* __restrict__ rw,
                       const float* __restrict__ ow) {
    int i = blockIdx.x * blockDim.x + threadIdx.x;
    if (i < EDIM*EDIM) {
        g_wq[i] = rtf(qw[i]);
        g_wb[i] = rtf(bw[i]);
        g_wp[i] = rtf(pw[i]);
    }
    if (i < 768*256) g_wr[i] = rtf(rw[i]);
    if (i < 64*768) {
        int ki = i / 768, oc = i % 768;
        g_wo[i] = ow[oc*64 + ki];
    }
}

// ---------------- bilinear resize 512 -> 1024 ----------------
__global__ void k_resize(const float* __restrict__ x) {
    int idx = blockIdx.x * blockDim.x + threadIdx.x;
    if (idx >= BATCHN*3*1024*1024) return;
    int ox = idx & 1023;
    int oy = (idx >> 10) & 1023;
    int ch = idx >> 20;
    float fy = oy * 0.5f - 0.25f;
    float fx = ox * 0.5f - 0.25f;
    int y0 = (int)floorf(fy); float ty = fy - (float)y0;
    int x0 = (int)floorf(fx); float tx = fx - (float)x0;
    int y1 = y0 + 1, x1 = x0 + 1;
    y0 = max(0, min(511, y0)); y1 = max(0, min(511, y1));
    x0 = max(0, min(511, x0)); x1 = max(0, min(511, x1));
    const float* p = x + (long)ch * 512 * 512;
    float v = p[y0*512+x0]*(1.f-ty)*(1.f-tx) + p[y0*512+x1]*(1.f-ty)*tx
            + p[y1*512+x0]*ty*(1.f-tx)       + p[y1*512+x1]*ty*tx;
    g_rx[idx] = rtf(v);
}

// ---------------- origin conv + fused LayerNorm -> g_opn ----------------
__global__ void k_conv_o(const float* __restrict__ x, const float* __restrict__ bias,
                         const float* __restrict__ lng, const float* __restrict__ lnb) {
    __shared__ float patch[16*192];                 // 12 KB
    __shared__ float red[768];                      // 24 warps x 16 p sums, then sumsq
    __shared__ float red2[768];
    __shared__ float stats[16][2];
    int b  = blockIdx.y;
    int y  = blockIdx.x >> 2;
    int xg = blockIdx.x & 3;
    int tid = threadIdx.x;                          // 768 = out channels
    int w = tid >> 5, lane = tid & 31;
    for (int e = tid; e < 16*192; e += 768) {
        int p = e / 192, r = e % 192;
        int c = r >> 6, pix = r & 63, py = pix >> 3, px = pix & 7;
        patch[e] = x[(((long)(b*3+c))*512 + y*8+py)*512 + (xg*16+p)*8+px];
    }
    __syncthreads();
    int g = tid >> 8;
    float acc[16];
    float bia = bias[tid];
#pragma unroll
    for (int p = 0; p < 16; p++) acc[p] = bia;
    const float* wt = g_wo + tid;
    const float* pg = patch + g*64;
#pragma unroll 8
    for (int i = 0; i < 64; i++) {
        float wv = wt[i*768];
#pragma unroll
        for (int p = 0; p < 16; p++)
            acc[p] += wv * pg[p*192 + i];
    }
    // fused LN over channel dim (768 threads) for each of 16 positions
#pragma unroll
    for (int p = 0; p < 16; p++) {
        float sv = acc[p], qv = acc[p]*acc[p];
        for (int o = 16; o; o >>= 1) {
            sv += __shfl_down_sync(0xffffffffu, sv, o);
            qv += __shfl_down_sync(0xffffffffu, qv, o);
        }
        if (lane == 0) { red[p*24 + w] = sv; red2[p*24 + w] = qv; }
    }
    __syncthreads();
    if (w < 16) {
        int p = w;
        float sv = (lane < 24) ? red[p*24 + lane]  : 0.f;
        float qv = (lane < 24) ? red2[p*24 + lane] : 0.f;
        for (int o = 16; o; o >>= 1) {
            sv += __shfl_down_sync(0xffffffffu, sv, o);
            qv += __shfl_down_sync(0xffffffffu, qv, o);
        }
        if (lane == 0) {
            float mu  = sv * (1.f/768.f);
            float var = qv * (1.f/768.f) - mu*mu;
            stats[p][0] = mu;
            stats[p][1] = rsqrtf(var + 1e-5f);
        }
    }
    __syncthreads();
    float gam = lng[tid], bet = lnb[tid];
#pragma unroll
    for (int p = 0; p < 16; p++) {
        int xq = xg*16 + p;
        int bwn = (b*2 + (y>>5))*2 + (xq>>5);
        int t   = (y&31)*32 + (xq&31);
        g_opn[((long)(bwn*LTOK + t))*EDIM + tid] =
            rtf((acc[p] - stats[p][0]) * stats[p][1] * gam + bet);
    }
}

// ---------------- LayerNorm (rp path only, output pre-rounded) ----------------
__global__ void k_ln(const float* __restrict__ gg, const float* __restrict__ bb) {
    long row = blockIdx.x;
    const float* r = g_rp + row * EDIM;
    float v[3], s = 0.f, ss = 0.f;
#pragma unroll
    for (int j = 0; j < 3; j++) {
        float xv = r[threadIdx.x + j*256];
        v[j] = xv; s += xv; ss += xv*xv;
    }
    __shared__ float shs[8], shss[8];
    for (int o = 16; o; o >>= 1) {
        s  += __shfl_down_sync(0xffffffffu, s,  o);
        ss += __shfl_down_sync(0xffffffffu, ss, o);
    }
    if ((threadIdx.x & 31) == 0) { shs[threadIdx.x>>5] = s; shss[threadIdx.x>>5] = ss; }
    __syncthreads();
    if (threadIdx.x < 8) {
        s = shs[threadIdx.x]; ss = shss[threadIdx.x];
        for (int o = 4; o; o >>= 1) {
            s  += __shfl_down_sync(0xffu, s,  o);
            ss += __shfl_down_sync(0xffu, ss, o);
        }
        if (threadIdx.x == 0) { shs[0] = s; shss[0] = ss; }
    }
    __syncthreads();
    float mu  = shs[0] * (1.f/768.f);
    float var = shss[0] * (1.f/768.f) - mu*mu;
    float rin = rsqrtf(var + 1e-5f);
#pragma unroll
    for (int j = 0; j < 3; j++) {
        int c = threadIdx.x + j*256;
        g_rpn[row*EDIM + c] = rtf((v[j]-mu)*rin*gg[c] + bb[c]);
    }
}

// ---------------- RoPE delta table ----------------
__global__ void k_gtab() {
    int tid = threadIdx.x;
    if (tid < 63) {
        float d = (float)(tid - 31);
        float s = 0.f;
#pragma unroll
        for (int f = 0; f < 16; f++)
            s += cosf(d * powf(10.0f, -(float)f / 16.0f));
        g_G[tid] = s;
    }
}

// ---------------- per-row inverse norms ----------------
__global__ void k_norm() {
    int z = blockIdx.x;
    int bwn = z >> 3, h = z & 7;
    const float* src = blockIdx.y ? g_bv : g_q;
    float* dst       = blockIdx.y ? g_inb : g_inq;
    int wid = threadIdx.x >> 5, lane = threadIdx.x & 31;
    for (int t = wid; t < LTOK; t += 8) {
        const float* r = src + ((long)(bwn*LTOK + t))*EDIM + h*HDIM;
        float s = 0.f;
#pragma unroll
        for (int j = 0; j < 3; j++) {
            float v = r[lane + 32*j];
            s += v*v;
        }
        for (int o = 16; o; o >>= 1) s += __shfl_down_sync(0xffffffffu, s, o);
        if (lane == 0) dst[z*LTOK + t] = rsqrtf(s + 32.0f);
    }
}

// ---------------- transpose pos_embed: [c][pos] -> [pos][c] ----------------
__global__ void k_tr_pe(const float* __restrict__ pe) {
    __shared__ float s[32][33];
    int c0 = blockIdx.x * 32, p0 = blockIdx.y * 32;
    int tx = threadIdx.x, ty = threadIdx.y;
#pragma unroll
    for (int j = 0; j < 4; j++)
        s[ty*4+j][tx] = pe[(long)(c0 + ty*4 + j)*4096 + p0 + tx];
    __syncthreads();
#pragma unroll
    for (int j = 0; j < 4; j++)
        g_pet[(long)(p0 + ty*4 + j)*EDIM + c0 + tx] = s[tx][ty*4+j];
}

// ================= tf32 mma.sync GEMM (NT) with 3-stage cp.async pipeline =================
// EPI 0: plain (+bias), output pre-rounded
// EPI 1: conv-r, A gathered from g_rx (fused im2col), -> g_rp
// EPI 2: final projection -> out (full fp32)
// EPI 3: av -> g_avt (pre-rounded)
// EPI 4: attn epilogue (pre-rounded)
// EPI 5: like EPI 0, plus fused transposed write -> g_bvt
#define LDK    36
#define TB     (128*LDK)
#define STAGES 3
#define SMEMSZ ((2*STAGES*TB + 64)*4)

__device__ __forceinline__ void cpa16(uint32_t d, const void* s) {
    asm volatile("cp.async.cg.shared.global [%0], [%1], 16;" :: "r"(d), "l"(s));
}
#define CP_COMMIT() asm volatile("cp.async.commit_group;" ::: "memory")
#define CP_WAIT1()  asm volatile("cp.async.wait_group 1;" ::: "memory")

__device__ __forceinline__ void mma8(float* d, const uint32_t* a, const uint32_t* b) {
    asm volatile(
        "mma.sync.aligned.m16n8k8.row.col.f32.tf32.tf32.f32 "
        "{%0,%1,%2,%3}, {%4,%5,%6,%7}, {%8,%9}, {%0,%1,%2,%3};"
        : "+f"(d[0]), "+f"(d[1]), "+f"(d[2]), "+f"(d[3])
        : "r"(a[0]), "r"(a[1]), "r"(a[2]), "r"(a[3]), "r"(b[0]), "r"(b[1]));
}

template<int EPI, int NMMA>
__global__ __launch_bounds__(256)
void tc_gemm(const float* __restrict__ A, const float* __restrict__ B,
             const float* __restrict__ bias, float* __restrict__ C,
             int K, int lda, int ldb, int ldc,
             long sA, long sB, long sC,
             const float* __restrict__ sr, const float* __restrict__ sc) {
    extern __shared__ __align__(16) float sm[];
    uint32_t sbase = (uint32_t)__cvta_generic_to_shared(sm);
    int tid = threadIdx.x;
    int wid = tid >> 5, lane = tid & 31;
    int tg = lane >> 2, t4 = lane & 3;
    long z = blockIdx.z;
    if (EPI == 4) {
        long off = (z >> 3) * (long)LTOK * EDIM + (z & 7) * HDIM;
        A += off; B += off;
        C += z * sC;
    } else {
        A += z * sA;
        if (EPI == 1) B += (z % 3) * 65536; else B += z * sB;
        if (EPI == 0 || EPI == 5) C += z * sC;
    }

    int row0 = blockIdx.y * 128, col0 = blockIdx.x * (32*NMMA);
    int wm = wid >> 2, wn = wid & 3;
    int m_base = wm * 64, n_base = wn * (8*NMMA);

    float acc[4][NMMA][4] = {};
    const int KT = K >> 5;

    int am[4], ac[4];
#pragma unroll
    for (int p = 0; p < 4; p++) {
        int i2 = tid + p*256;
        am[p] = i2 >> 3;
        ac[p] = (i2 & 7) << 2;
    }

    auto fill = [&](int kt) {
        int stg = kt % STAGES;
        int k0 = kt << 5;
        uint32_t ab = sbase + (uint32_t)(stg * (2*TB)) * 4u;
        uint32_t bb = ab + TB*4u;
#pragma unroll
        for (int p = 0; p < 4; p++) {
            const float* srcA;
            if (EPI == 1) {
                int pos = row0 + am[p];
                int y = pos >> 6, xq = pos & 63;
                int k = k0 + ac[p];
                int py = k >> 4, px = k & 15;
                srcA = g_rx + ((long)z*1024 + y*16 + py)*1024 + xq*16 + px;
            } else {
                srcA = A + (long)(row0 + am[p])*lda + k0 + ac[p];
            }
            cpa16(ab + (uint32_t)(am[p]*LDK + ac[p])*4u, srcA);
        }
#pragma unroll
        for (int p = 0; p < NMMA; p++)
            cpa16(bb + (uint32_t)(am[p]*LDK + ac[p])*4u,
                  B + (long)(col0 + am[p])*ldb + k0 + ac[p]);
    };

    fill(0); CP_COMMIT();
    fill(1); CP_COMMIT();

    for (int kt = 0; kt < KT; kt++) {
        CP_WAIT1();
        __syncthreads();
        if (kt + 2 < KT) fill(kt + 2);
        CP_COMMIT();
        const float* As = sm + (kt % STAGES) * (2*TB);
        const float* Bs = As + TB;
#pragma unroll
        for (int ks = 0; ks < 4; ks++) {
            int kk = ks*8 + t4;
            const float* A0 = As + (m_base + tg)*LDK + kk;
            const float* B0 = Bs + (n_base + tg)*LDK + kk;
            uint32_t af[4][4], bf[NMMA][2];
#pragma unroll
            for (int im = 0; im < 4; im++) {
                af[im][0] = __float_as_uint(A0[im*16*LDK]);
                af[im][1] = __float_as_uint(A0[im*16*LDK + 8*LDK]);
                af[im][2] = __float_as_uint(A0[im*16*LDK + 4]);
                af[im][3] = __float_as_uint(A0[im*16*LDK + 8*LDK + 4]);
            }
#pragma unroll
            for (int in = 0; in < NMMA; in++) {
                bf[in][0] = __float_as_uint(B0[in*8*LDK]);
                bf[in][1] = __float_as_uint(B0[in*8*LDK + 4]);
            }
#pragma unroll
            for (int im = 0; im < 4; im++)
#pragma unroll
                for (int in = 0; in < NMMA; in++)
                    mma8(acc[im][in], af[im], bf[in]);
        }
    }

    __syncthreads();
    if (EPI == 4 && tid < 63) sm[2*STAGES*TB + tid] = g_G[tid];
#pragma unroll
    for (int im = 0; im < 4; im++) {
#pragma unroll
        for (int in = 0; in < NMMA; in++) {
            int r = m_base + im*16 + tg;
            int c = n_base + in*8 + t4*2;
            int s0 = ((c >> 2) ^ (r & 31));
            float* p0 = sm + (r << 7) + (s0 << 2) + (c & 3);
            p0[0] = acc[im][in][0]; p0[1] = acc[im][in][1];
            int r2 = r + 8;
            int s2 = ((c >> 2) ^ (r2 & 31));
            float* p2 = sm + (r2 << 7) + (s2 << 2) + (c & 3);
            p2[0] = acc[im][in][2]; p2[1] = acc[im][in][3];
        }
    }
    __syncthreads();

#pragma unroll 1
    for (int pass = 0; pass < 16; pass++) {
        int r  = pass*8 + wid;
        int c4 = lane;
        if (NMMA == 3 && c4 >= 24) continue;
        int slot = c4 ^ (r & 31);
        float4 v = *(const float4*)(sm + (r << 7) + (slot << 2));
        int row = row0 + r;
        int col = col0 + (c4 << 2);
        if (EPI == 0 || EPI == 5) {
            if (bias) { v.x += bias[col]; v.y += bias[col+1]; v.z += bias[col+2]; v.w += bias[col+3]; }
            *(float4*)(C + (long)row*ldc + col) = cvt4(v);
        } else if (EPI == 1) {
            int pos = row;
            int y = pos >> 6, xq = pos & 63;
            int bb_ = (int)(z / 3), g = (int)(z % 3);
            int bwn = (bb_*2 + (y>>5))*2 + (xq>>5);
            int t   = (y&31)*32 + (xq&31);
            int cc  = g*256 + col;
            float4 pb4 = *(const float4*)(g_pet + (long)pos*EDIM + cc);
            v.x += bias[cc+0] + pb4.x; v.y += bias[cc+1] + pb4.y;
            v.z += bias[cc+2] + pb4.z; v.w += bias[cc+3] + pb4.w;
            *(float4*)(g_rp + ((long)(bwn*LTOK + t))*EDIM + cc) = v;
        } else if (EPI == 2) {
            int oc = row, tok = col;
            int bb_ = tok >> 12, p = tok & 4095;
            float bia = bias[oc];
            v.x += bia; v.y += bia; v.z += bia; v.w += bia;
            *(float4*)(C + (long)bb_*(EDIM*4096) + (long)oc*4096 + p) = v;
        } else if (EPI == 3) {
            int bwn = (int)(z >> 3), h = (int)(z & 7);
            int t = row;
            int b_ = bwn >> 2, wy = (bwn >> 1) & 1, wx = bwn & 1;
            int ly = t >> 5, lx = t & 31;
            int tok = b_*4096 + (wy*32 + ly)*64 + (wx*32 + lx);
            *(float4*)(g_avt + (long)tok*EDIM + h*HDIM + (c4 << 2)) = cvt4(v);
        } else { // EPI 4
            const float* smG = sm + 2*STAGES*TB;
            int xi = row & 31, yi = row >> 5;
            float iq = sr[z*LTOK + row];
            float4 ib4 = *(const float4*)(sc + z*LTOK + col);
            int xj0 = col & 31, yj0 = col >> 5;
            v.x = (v.x + smG[xi - xj0     + 31] + smG[yi - yj0 + 31]) * iq * ib4.x;
            v.y = (v.y + smG[xi - (xj0+1) + 31] + smG[yi - yj0 + 31]) * iq * ib4.y;
            v.z = (v.z + smG[xi - (xj0+2) + 31] + smG[yi - yj0 + 31]) * iq * ib4.z;
            v.w = (v.w + smG[xi - (xj0+3) + 31] + smG[yi - yj0 + 31]) * iq * ib4.w;
            *(float4*)(C + (long)row*ldc + col) = cvt4(v);
        }
    }

    if (EPI == 5) {
        // fused transposed write -> g_bvt[(bwn*8+h)*96+d][t]
        int bwn = row0 >> 10;
        int t0  = row0 & 1023;
#pragma unroll 1
        for (int cc = 0; cc < 16; cc++) {
            int cI = wid*16 + cc;
            int ch = col0 + cI;
            int h = ch / 96, d = ch - h*96;
            float bia = bias[ch];
            float vv[4];
#pragma unroll
            for (int i = 0; i < 4; i++) {
                int r = 4*lane + i;
                int slot = (cI >> 2) ^ (r & 31);
                vv[i] = rtf(sm[(r << 7) + (slot << 2) + (cI & 3)] + bia);
            }
            float4 o4 = {vv[0], vv[1], vv[2], vv[3]};
            *(float4*)(g_bvt + ((long)(bwn*8 + h)*96 + d)*1024 + t0 + 4*lane) = o4;
        }
    }
}

// ---------------- host launch ----------------
static float* sym_addr(const void* sym) {
    void* p = nullptr;
    cudaGetSymbolAddress(&p, sym);
    return (float*)p;
}

extern "C" void kernel_launch(void* const* d_in, const int* in_sizes, int n_in,
                              void* d_out, int out_size) {
    const float* x      = (const float*)d_in[0];
    const float* ow     = (const float*)d_in[1];
    const float* obias  = (const float*)d_in[2];
    const float* rw     = (const float*)d_in[3];
    const float* rbias  = (const float*)d_in[4];
    const float* pe     = (const float*)d_in[5];
    const float* nb_g   = (const float*)d_in[6];
    const float* nb_b   = (const float*)d_in[7];
    const float* nq_g   = (const float*)d_in[8];
    const float* nq_b   = (const float*)d_in[9];
    const float* qw     = (const float*)d_in[10];
    const float* qb     = (const float*)d_in[11];
    const float* bw     = (const float*)d_in[12];
    const float* bb     = (const float*)d_in[13];
    const float* projw  = (const float*)d_in[14];
    const float* projb  = (const float*)d_in[15];

    float* out  = (float*)d_out;
    float* attn = out + OUT_ELEMS;

    float* p_rx  = sym_addr(g_rx);
    float* p_rpn = sym_addr(g_rpn);
    float* p_opn = sym_addr(g_opn);
    float* p_q   = sym_addr(g_q);
    float* p_bv  = sym_addr(g_bv);
    float* p_avt = sym_addr(g_avt);
    float* p_bvt = sym_addr(g_bvt);
    float* p_inq = sym_addr(g_inq);
    float* p_inb = sym_addr(g_inb);
    float* p_wq  = sym_addr(g_wq);
    float* p_wb  = sym_addr(g_wb);
    float* p_wp  = sym_addr(g_wp);
    float* p_wr  = sym_addr(g_wr);

    cudaFuncSetAttribute(tc_gemm<0,4>, cudaFuncAttributeMaxDynamicSharedMemorySize, SMEMSZ);
    cudaFuncSetAttribute(tc_gemm<1,4>, cudaFuncAttributeMaxDynamicSharedMemorySize, SMEMSZ);
    cudaFuncSetAttribute(tc_gemm<2,4>, cudaFuncAttributeMaxDynamicSharedMemorySize, SMEMSZ);
    cudaFuncSetAttribute(tc_gemm<3,3>, cudaFuncAttributeMaxDynamicSharedMemorySize, SMEMSZ);
    cudaFuncSetAttribute(tc_gemm<4,4>, cudaFuncAttributeMaxDynamicSharedMemorySize, SMEMSZ);
    cudaFuncSetAttribute(tc_gemm<5,4>, cudaFuncAttributeMaxDynamicSharedMemorySize, SMEMSZ);

    k_cvtw<<<2304, 256>>>(qw, bw, projw, rw, ow);                      // 1
    k_resize<<<24576, 256>>>(x);                                       // 2
    k_tr_pe<<<dim3(24, 128), dim3(32, 8)>>>(pe);                       // 3
    // resize conv as tf32 GEMM with fused im2col gather
    tc_gemm<1,4><<<dim3(2, 32, 6), 256, SMEMSZ>>>(p_rx, p_wr, rbias, nullptr,
                                                  256, 256, 256, 0,
                                                  0, 0, 0, nullptr, nullptr);   // 4
    k_ln<<<BWIN*LTOK, 256>>>(nq_g, nq_b);                              // 5
    // q projection <- profiled launch (#6)
    tc_gemm<0,4><<<dim3(6, 64, 1), 256, SMEMSZ>>>(p_rpn, p_wq, qb, p_q,
                                                  EDIM, EDIM, EDIM, EDIM, 0, 0, 0,
                                                  nullptr, nullptr);   // 6
    // origin conv + fused LN -> g_opn
    k_conv_o<<<dim3(256, BATCHN), 768>>>(x, obias, nb_g, nb_b);        // 7
    // b projection with fused transpose -> g_bv + g_bvt
    tc_gemm<5,4><<<dim3(6, 64, 1), 256, SMEMSZ>>>(p_opn, p_wb, bb, p_bv,
                                                  EDIM, EDIM, EDIM, EDIM, 0, 0, 0,
                                                  nullptr, nullptr);   // 8
    k_gtab<<<1, 64>>>();                                               // 9
    k_norm<<<dim3(BWIN*NHEADS, 2), 256>>>();                           // 10
    // attn = (q96·b96 + G) * inq * inb -> second output region
    tc_gemm<4,4><<<dim3(8, 8, BWIN*NHEADS), 256, SMEMSZ>>>(p_q, p_bv, nullptr, attn,
                                                           HDIM, EDIM, EDIM, LTOK,
                                                           0, 0, (long)LTOK*LTOK,
                                                           p_inq, p_inb);       // 11
    // av = attn @ b (N=96 exact) -> g_avt
    tc_gemm<3,3><<<dim3(1, 8, BWIN*NHEADS), 256, SMEMSZ>>>(attn, p_bvt, nullptr, nullptr,
                                                           LTOK, LTOK, LTOK, 0,
                                                           (long)LTOK*LTOK, (long)HDIM*LTOK, 0,
                                                           nullptr, nullptr);   // 12
    // final projection -> first output region
    tc_gemm<2,4><<<dim3(64, 6, 1), 256, SMEMSZ>>>(p_wp, p_avt, projb, out,
                                                  EDIM, EDIM, EDIM, 0, 0, 0, 0,
                                                  nullptr, nullptr);   // 13
}

// round 10
// speedup vs baseline: 1.0636x; 1.0636x over previous
#include <cuda_runtime.h>
#include <math.h>
#include <stdint.h>

// ---------------- problem constants ----------------
#define BATCHN  2
#define EDIM    768
#define LTOK    1024
#define BWIN    8
#define NHEADS  8
#define HDIM    96
#define OUT_ELEMS (BATCHN*EDIM*64*64)

// ---------------- scratch ----------------
__device__ float g_rx [BATCHN*3*1024*1024];
__device__ float g_op [BWIN*LTOK*EDIM];
__device__ float g_rp [BWIN*LTOK*EDIM];
__device__ float g_opn[BWIN*LTOK*EDIM];
__device__ float g_rpn[BWIN*LTOK*EDIM];
__device__ float g_q  [BWIN*LTOK*EDIM];
__device__ float g_bv [BWIN*LTOK*EDIM];
__device__ float g_avt[BATCHN*4096*EDIM];
__device__ float g_bvt[BWIN*NHEADS*HDIM*LTOK];
__device__ float g_pet[4096*EDIM];
__device__ float g_inq[BWIN*NHEADS*LTOK];
__device__ float g_inb[BWIN*NHEADS*LTOK];
__device__ float g_G  [64];
// tf32-pre-rounded weights
__device__ float g_wq[EDIM*EDIM];
__device__ float g_wb[EDIM*EDIM];
__device__ float g_wp[EDIM*EDIM];
__device__ float g_wr[768*256];
__device__ float g_wo[64*768];     // origin conv weights transposed [i][oc], fp32

__device__ __forceinline__ uint32_t f2tf32(float f) {
    uint32_t u;
    asm("cvt.rna.tf32.f32 %0, %1;" : "=r"(u) : "f"(f));
    return u;
}
__device__ __forceinline__ float rtf(float f) { return __uint_as_float(f2tf32(f)); }
__device__ __forceinline__ float4 cvt4(float4 v) {
    v.x = rtf(v.x); v.y = rtf(v.y); v.z = rtf(v.z); v.w = rtf(v.w);
    return v;
}

// ---------------- weight pre-rounding + origin-weight transpose ----------------
__global__ void k_cvtw(const float* __restrict__ qw, const float* __restrict__ bw,
                       const float* __restrict__ pw, const float* __restrict__ rw,
                       const float* __restrict__ ow) {
    int i = blockIdx.x * blockDim.x + threadIdx.x;
    if (i < EDIM*EDIM) {
        g_wq[i] = rtf(qw[i]);
        g_wb[i] = rtf(bw[i]);
        g_wp[i] = rtf(pw[i]);
    }
    if (i < 768*256) g_wr[i] = rtf(rw[i]);
    if (i < 64*768) {
        int ki = i / 768, oc = i % 768;
        g_wo[i] = ow[oc*64 + ki];
    }
}

// ---------------- bilinear resize 512 -> 1024 ----------------
__global__ void k_resize(const float* __restrict__ x) {
    int idx = blockIdx.x * blockDim.x + threadIdx.x;
    if (idx >= BATCHN*3*1024*1024) return;
    int ox = idx & 1023;
    int oy = (idx >> 10) & 1023;
    int ch = idx >> 20;
    float fy = oy * 0.5f - 0.25f;
    float fx = ox * 0.5f - 0.25f;
    int y0 = (int)floorf(fy); float ty = fy - (float)y0;
    int x0 = (int)floorf(fx); float tx = fx - (float)x0;
    int y1 = y0 + 1, x1 = x0 + 1;
    y0 = max(0, min(511, y0)); y1 = max(0, min(511, y1));
    x0 = max(0, min(511, x0)); x1 = max(0, min(511, x1));
    const float* p = x + (long)ch * 512 * 512;
    float v = p[y0*512+x0]*(1.f-ty)*(1.f-tx) + p[y0*512+x1]*(1.f-ty)*tx
            + p[y1*512+x0]*ty*(1.f-tx)       + p[y1*512+x1]*ty*tx;
    g_rx[idx] = rtf(v);
}

// ---------------- origin conv (round-8 version) ----------------
__global__ void k_conv_o(const float* __restrict__ x, const float* __restrict__ bias) {
    __shared__ float patch[16*192];
    int b  = blockIdx.y;
    int y  = blockIdx.x >> 2;
    int xg = blockIdx.x & 3;
    int tid = threadIdx.x;
    for (int e = tid; e < 16*192; e += 768) {
        int p = e / 192, r = e % 192;
        int c = r >> 6, pix = r & 63, py = pix >> 3, px = pix & 7;
        patch[e] = x[(((long)(b*3+c))*512 + y*8+py)*512 + (xg*16+p)*8+px];
    }
    __syncthreads();
    int g = tid >> 8;
    float acc[16];
    float bia = bias[tid];
#pragma unroll
    for (int p = 0; p < 16; p++) acc[p] = bia;
    const float* wt = g_wo + tid;
    const float* pg = patch + g*64;
#pragma unroll 8
    for (int i = 0; i < 64; i++) {
        float wv = wt[i*768];
#pragma unroll
        for (int p = 0; p < 16; p++)
            acc[p] += wv * pg[p*192 + i];
    }
#pragma unroll
    for (int p = 0; p < 16; p++) {
        int xq = xg*16 + p;
        int bwn = (b*2 + (y>>5))*2 + (xq>>5);
        int t   = (y&31)*32 + (xq&31);
        g_op[((long)(bwn*LTOK + t))*EDIM + tid] = acc[p];
    }
}

// ---------------- LayerNorm (both paths, round-8 version) ----------------
__global__ void k_ln(const float* __restrict__ g0, const float* __restrict__ b0,
                     const float* __restrict__ g1, const float* __restrict__ b1) {
    long row = blockIdx.x;
    const float* in = blockIdx.y ? g_rp : g_op;
    const float* gg = blockIdx.y ? g1 : g0;
    const float* bb = blockIdx.y ? b1 : b0;
    float* out = blockIdx.y ? g_rpn : g_opn;
    const float* r = in + row * EDIM;
    float v[3], s = 0.f, ss = 0.f;
#pragma unroll
    for (int j = 0; j < 3; j++) {
        float xv = r[threadIdx.x + j*256];
        v[j] = xv; s += xv; ss += xv*xv;
    }
    __shared__ float shs[8], shss[8];
    for (int o = 16; o; o >>= 1) {
        s  += __shfl_down_sync(0xffffffffu, s,  o);
        ss += __shfl_down_sync(0xffffffffu, ss, o);
    }
    if ((threadIdx.x & 31) == 0) { shs[threadIdx.x>>5] = s; shss[threadIdx.x>>5] = ss; }
    __syncthreads();
    if (threadIdx.x < 8) {
        s = shs[threadIdx.x]; ss = shss[threadIdx.x];
        for (int o = 4; o; o >>= 1) {
            s  += __shfl_down_sync(0xffu, s,  o);
            ss += __shfl_down_sync(0xffu, ss, o);
        }
        if (threadIdx.x == 0) { shs[0] = s; shss[0] = ss; }
    }
    __syncthreads();
    float mu  = shs[0] * (1.f/768.f);
    float var = shss[0] * (1.f/768.f) - mu*mu;
    float rin = rsqrtf(var + 1e-5f);
#pragma unroll
    for (int j = 0; j < 3; j++) {
        int c = threadIdx.x + j*256;
        out[row*EDIM + c] = rtf((v[j]-mu)*rin*gg[c] + bb[c]);
    }
}

// ---------------- RoPE delta table ----------------
__global__ void k_gtab() {
    int tid = threadIdx.x;
    if (tid < 63) {
        float d = (float)(tid - 31);
        float s = 0.f;
#pragma unroll
        for (int f = 0; f < 16; f++)
            s += cosf(d * powf(10.0f, -(float)f / 16.0f));
        g_G[tid] = s;
    }
}

// ---------------- per-row inverse norms ----------------
__global__ void k_norm() {
    int z = blockIdx.x;
    int bwn = z >> 3, h = z & 7;
    const float* src = blockIdx.y ? g_bv : g_q;
    float* dst       = blockIdx.y ? g_inb : g_inq;
    int wid = threadIdx.x >> 5, lane = threadIdx.x & 31;
    for (int t = wid; t < LTOK; t += 8) {
        const float* r = src + ((long)(bwn*LTOK + t))*EDIM + h*HDIM;
        float s = 0.f;
#pragma unroll
        for (int j = 0; j < 3; j++) {
            float v = r[lane + 32*j];
            s += v*v;
        }
        for (int o = 16; o; o >>= 1) s += __shfl_down_sync(0xffffffffu, s, o);
        if (lane == 0) dst[z*LTOK + t] = rsqrtf(s + 32.0f);
    }
}

// ---------------- transpose b per (bwn,h): [t][d] -> [d][t] ----------------
__global__ void k_tr_bv() {
    __shared__ float s[32][33];
    int z = blockIdx.z; int bwn = z >> 3, h = z & 7;
    int d0 = blockIdx.x * 32, t0 = blockIdx.y * 32;
    int tx = threadIdx.x, ty = threadIdx.y;
#pragma unroll
    for (int j = 0; j < 4; j++) {
        int t = t0 + ty*4 + j;
        s[ty*4+j][tx] = g_bv[((long)(bwn*LTOK + t))*EDIM + h*HDIM + d0 + tx];
    }
    __syncthreads();
#pragma unroll
    for (int j = 0; j < 4; j++) {
        int d = d0 + ty*4 + j;
        g_bvt[((long)(z*HDIM + d))*LTOK + t0 + tx] = s[tx][ty*4+j];
    }
}

// ---------------- transpose pos_embed: [c][pos] -> [pos][c] ----------------
__global__ void k_tr_pe(const float* __restrict__ pe) {
    __shared__ float s[32][33];
    int c0 = blockIdx.x * 32, p0 = blockIdx.y * 32;
    int tx = threadIdx.x, ty = threadIdx.y;
#pragma unroll
    for (int j = 0; j < 4; j++)
        s[ty*4+j][tx] = pe[(long)(c0 + ty*4 + j)*4096 + p0 + tx];
    __syncthreads();
#pragma unroll
    for (int j = 0; j < 4; j++)
        g_pet[(long)(p0 + ty*4 + j)*EDIM + c0 + tx] = s[tx][ty*4+j];
}

// ================= tf32 mma.sync GEMM (NT), cp.async pipeline + ldmatrix frags =========
#define LDK    36
#define TB     (128*LDK)
#define STAGES 3
#define SMEMSZ ((2*STAGES*TB + 64)*4)

__device__ __forceinline__ void cpa16(uint32_t d, const void* s) {
    asm volatile("cp.async.cg.shared.global [%0], [%1], 16;" :: "r"(d), "l"(s));
}
#define CP_COMMIT() asm volatile("cp.async.commit_group;" ::: "memory")
#define CP_WAIT1()  asm volatile("cp.async.wait_group 1;" ::: "memory")

__device__ __forceinline__ void mma8(float* d, const uint32_t* a, const uint32_t* b) {
    asm volatile(
        "mma.sync.aligned.m16n8k8.row.col.f32.tf32.tf32.f32 "
        "{%0,%1,%2,%3}, {%4,%5,%6,%7}, {%8,%9}, {%0,%1,%2,%3};"
        : "+f"(d[0]), "+f"(d[1]), "+f"(d[2]), "+f"(d[3])
        : "r"(a[0]), "r"(a[1]), "r"(a[2]), "r"(a[3]), "r"(b[0]), "r"(b[1]));
}
__device__ __forceinline__ void ldsm4(uint32_t* r, uint32_t addr) {
    asm volatile("ldmatrix.sync.aligned.m8n8.x4.shared.b16 {%0,%1,%2,%3}, [%4];"
        : "=r"(r[0]), "=r"(r[1]), "=r"(r[2]), "=r"(r[3]) : "r"(addr));
}
__device__ __forceinline__ void ldsm2(uint32_t* r, uint32_t addr) {
    asm volatile("ldmatrix.sync.aligned.m8n8.x2.shared.b16 {%0,%1}, [%2];"
        : "=r"(r[0]), "=r"(r[1]) : "r"(addr));
}

template<int EPI, int NMMA>
__global__ __launch_bounds__(256)
void tc_gemm(const float* __restrict__ A, const float* __restrict__ B,
             const float* __restrict__ bias, float* __restrict__ C,
             int K, int lda, int ldb, int ldc,
             long sA, long sB, long sC,
             const float* __restrict__ sr, const float* __restrict__ sc) {
    extern __shared__ __align__(16) float sm[];
    uint32_t sbase = (uint32_t)__cvta_generic_to_shared(sm);
    int tid = threadIdx.x;
    int wid = tid >> 5, lane = tid & 31;
    int tg = lane >> 2, t4 = lane & 3;
    long z = blockIdx.z;
    if (EPI == 4) {
        long off = (z >> 3) * (long)LTOK * EDIM + (z & 7) * HDIM;
        A += off; B += off;
        C += z * sC;
    } else {
        A += z * sA;
        if (EPI == 1) B += (z % 3) * 65536; else B += z * sB;
        if (EPI == 0) C += z * sC;
    }

    int row0 = blockIdx.y * 128, col0 = blockIdx.x * (32*NMMA);
    int wm = wid >> 2, wn = wid & 3;
    int m_base = wm * 64, n_base = wn * (8*NMMA);

    float acc[4][NMMA][4] = {};
    const int KT = K >> 5;

    int am[4], ac[4];
#pragma unroll
    for (int p = 0; p < 4; p++) {
        int i2 = tid + p*256;
        am[p] = i2 >> 3;
        ac[p] = (i2 & 7) << 2;
    }

    // ldmatrix per-thread base offsets (bytes, relative to stage base)
    int quad = lane >> 3, l8 = lane & 7;
    uint32_t aoffB = (uint32_t)(((m_base + l8 + ((quad & 1) << 3))*LDK + ((quad >> 1) << 2)) * 4);
    int bl = lane & 15;
    uint32_t boffB = (uint32_t)((TB + (n_base + (bl & 7))*LDK + ((bl >> 3) << 2)) * 4);

    auto fill = [&](int kt) {
        int stg = kt % STAGES;
        int k0 = kt << 5;
        uint32_t ab = sbase + (uint32_t)(stg * (2*TB)) * 4u;
        uint32_t bb = ab + TB*4u;
#pragma unroll
        for (int p = 0; p < 4; p++) {
            const float* srcA;
            if (EPI == 1) {
                int pos = row0 + am[p];
                int y = pos >> 6, xq = pos & 63;
                int k = k0 + ac[p];
                int py = k >> 4, px = k & 15;
                srcA = g_rx + ((long)z*1024 + y*16 + py)*1024 + xq*16 + px;
            } else {
                srcA = A + (long)(row0 + am[p])*lda + k0 + ac[p];
            }
            cpa16(ab + (uint32_t)(am[p]*LDK + ac[p])*4u, srcA);
        }
#pragma unroll
        for (int p = 0; p < NMMA; p++)
            cpa16(bb + (uint32_t)(am[p]*LDK + ac[p])*4u,
                  B + (long)(col0 + am[p])*ldb + k0 + ac[p]);
    };

    fill(0); CP_COMMIT();
    fill(1); CP_COMMIT();

    for (int kt = 0; kt < KT; kt++) {
        CP_WAIT1();
        __syncthreads();
        if (kt + 2 < KT) fill(kt + 2);
        CP_COMMIT();
        uint32_t stgoff = sbase + (uint32_t)((kt % STAGES) * (2*TB)) * 4u;
#pragma unroll
        for (int ks = 0; ks < 4; ks++) {
            uint32_t af[4][4], bf[NMMA][2];
#pragma unroll
            for (int im = 0; im < 4; im++)
                ldsm4(af[im], stgoff + aoffB + (uint32_t)((im*16*LDK + ks*8)*4));
#pragma unroll
            for (int in = 0; in < NMMA; in++)
                ldsm2(bf[in], stgoff + boffB + (uint32_t)((in*8*LDK + ks*8)*4));
#pragma unroll
            for (int im = 0; im < 4; im++)
#pragma unroll
                for (int in = 0; in < NMMA; in++)
                    mma8(acc[im][in], af[im], bf[in]);
        }
    }

    __syncthreads();
    if (EPI == 4 && tid < 63) sm[2*STAGES*TB + tid] = g_G[tid];
#pragma unroll
    for (int im = 0; im < 4; im++) {
#pragma unroll
        for (int in = 0; in < NMMA; in++) {
            int r = m_base + im*16 + tg;
            int c = n_base + in*8 + t4*2;
            int s0 = ((c >> 2) ^ (r & 31));
            float* p0 = sm + (r << 7) + (s0 << 2) + (c & 3);
            p0[0] = acc[im][in][0]; p0[1] = acc[im][in][1];
            int r2 = r + 8;
            int s2 = ((c >> 2) ^ (r2 & 31));
            float* p2 = sm + (r2 << 7) + (s2 << 2) + (c & 3);
            p2[0] = acc[im][in][2]; p2[1] = acc[im][in][3];
        }
    }
    __syncthreads();

#pragma unroll 1
    for (int pass = 0; pass < 16; pass++) {
        int r  = pass*8 + wid;
        int c4 = lane;
        if (NMMA == 3 && c4 >= 24) continue;
        int slot = c4 ^ (r & 31);
        float4 v = *(const float4*)(sm + (r << 7) + (slot << 2));
        int row = row0 + r;
        int col = col0 + (c4 << 2);
        if (EPI == 0) {
            if (bias) { v.x += bias[col]; v.y += bias[col+1]; v.z += bias[col+2]; v.w += bias[col+3]; }
            *(float4*)(C + (long)row*ldc + col) = cvt4(v);
        } else if (EPI == 1) {
            int pos = row;
            int y = pos >> 6, xq = pos & 63;
            int bb_ = (int)(z / 3), g = (int)(z % 3);
            int bwn = (bb_*2 + (y>>5))*2 + (xq>>5);
            int t   = (y&31)*32 + (xq&31);
            int cc  = g*256 + col;
            float4 pb4 = *(const float4*)(g_pet + (long)pos*EDIM + cc);
            v.x += bias[cc+0] + pb4.x; v.y += bias[cc+1] + pb4.y;
            v.z += bias[cc+2] + pb4.z; v.w += bias[cc+3] + pb4.w;
            *(float4*)(g_rp + ((long)(bwn*LTOK + t))*EDIM + cc) = v;
        } else if (EPI == 2) {
            int oc = row, tok = col;
            int bb_ = tok >> 12, p = tok & 4095;
            float bia = bias[oc];
            v.x += bia; v.y += bia; v.z += bia; v.w += bia;
            *(float4*)(C + (long)bb_*(EDIM*4096) + (long)oc*4096 + p) = v;
        } else if (EPI == 3) {
            int bwn = (int)(z >> 3), h = (int)(z & 7);
            int t = row;
            int b_ = bwn >> 2, wy = (bwn >> 1) & 1, wx = bwn & 1;
            int ly = t >> 5, lx = t & 31;
            int tok = b_*4096 + (wy*32 + ly)*64 + (wx*32 + lx);
            *(float4*)(g_avt + (long)tok*EDIM + h*HDIM + (c4 << 2)) = cvt4(v);
        } else { // EPI 4
            const float* smG = sm + 2*STAGES*TB;
            int xi = row & 31, yi = row >> 5;
            float iq = sr[z*LTOK + row];
            float4 ib4 = *(const float4*)(sc + z*LTOK + col);
            int xj0 = col & 31, yj0 = col >> 5;
            v.x = (v.x + smG[xi - xj0     + 31] + smG[yi - yj0 + 31]) * iq * ib4.x;
            v.y = (v.y + smG[xi - (xj0+1) + 31] + smG[yi - yj0 + 31]) * iq * ib4.y;
            v.z = (v.z + smG[xi - (xj0+2) + 31] + smG[yi - yj0 + 31]) * iq * ib4.z;
            v.w = (v.w + smG[xi - (xj0+3) + 31] + smG[yi - yj0 + 31]) * iq * ib4.w;
            *(float4*)(C + (long)row*ldc + col) = cvt4(v);
        }
    }
}

// ---------------- host launch ----------------
static float* sym_addr(const void* sym) {
    void* p = nullptr;
    cudaGetSymbolAddress(&p, sym);
    return (float*)p;
}

extern "C" void kernel_launch(void* const* d_in, const int* in_sizes, int n_in,
                              void* d_out, int out_size) {
    const float* x      = (const float*)d_in[0];
    const float* ow     = (const float*)d_in[1];
    const float* obias  = (const float*)d_in[2];
    const float* rw     = (const float*)d_in[3];
    const float* rbias  = (const float*)d_in[4];
    const float* pe     = (const float*)d_in[5];
    const float* nb_g   = (const float*)d_in[6];
    const float* nb_b   = (const float*)d_in[7];
    const float* nq_g   = (const float*)d_in[8];
    const float* nq_b   = (const float*)d_in[9];
    const float* qw     = (const float*)d_in[10];
    const float* qb     = (const float*)d_in[11];
    const float* bw     = (const float*)d_in[12];
    const float* bb     = (const float*)d_in[13];
    const float* projw  = (const float*)d_in[14];
    const float* projb  = (const float*)d_in[15];

    float* out  = (float*)d_out;
    float* attn = out + OUT_ELEMS;

    float* p_rx  = sym_addr(g_rx);
    float* p_rpn = sym_addr(g_rpn);
    float* p_opn = sym_addr(g_opn);
    float* p_q   = sym_addr(g_q);
    float* p_bv  = sym_addr(g_bv);
    float* p_avt = sym_addr(g_avt);
    float* p_bvt = sym_addr(g_bvt);
    float* p_inq = sym_addr(g_inq);
    float* p_inb = sym_addr(g_inb);
    float* p_wq  = sym_addr(g_wq);
    float* p_wb  = sym_addr(g_wb);
    float* p_wp  = sym_addr(g_wp);
    float* p_wr  = sym_addr(g_wr);

    cudaFuncSetAttribute(tc_gemm<0,4>, cudaFuncAttributeMaxDynamicSharedMemorySize, SMEMSZ);
    cudaFuncSetAttribute(tc_gemm<1,4>, cudaFuncAttributeMaxDynamicSharedMemorySize, SMEMSZ);
    cudaFuncSetAttribute(tc_gemm<2,4>, cudaFuncAttributeMaxDynamicSharedMemorySize, SMEMSZ);
    cudaFuncSetAttribute(tc_gemm<3,3>, cudaFuncAttributeMaxDynamicSharedMemorySize, SMEMSZ);
    cudaFuncSetAttribute(tc_gemm<4,4>, cudaFuncAttributeMaxDynamicSharedMemorySize, SMEMSZ);

    k_cvtw<<<2304, 256>>>(qw, bw, projw, rw, ow);                      // 1
    k_resize<<<24576, 256>>>(x);                                       // 2
    k_tr_pe<<<dim3(24, 128), dim3(32, 8)>>>(pe);                       // 3
    // resize conv as tf32 GEMM with fused im2col gather  <- profiled (#4)
    tc_gemm<1,4><<<dim3(2, 32, 6), 256, SMEMSZ>>>(p_rx, p_wr, rbias, nullptr,
                                                  256, 256, 256, 0,
                                                  0, 0, 0, nullptr, nullptr);   // 4
    k_conv_o<<<dim3(256, BATCHN), 768>>>(x, obias);                    // 5
    k_ln<<<dim3(BWIN*LTOK, 2), 256>>>(nb_g, nb_b, nq_g, nq_b);         // 6
    tc_gemm<0,4><<<dim3(6, 64, 1), 256, SMEMSZ>>>(p_rpn, p_wq, qb, p_q,
                                                  EDIM, EDIM, EDIM, EDIM, 0, 0, 0,
                                                  nullptr, nullptr);   // 7
    tc_gemm<0,4><<<dim3(6, 64, 1), 256, SMEMSZ>>>(p_opn, p_wb, bb, p_bv,
                                                  EDIM, EDIM, EDIM, EDIM, 0, 0, 0,
                                                  nullptr, nullptr);   // 8
    k_gtab<<<1, 64>>>();                                               // 9
    k_norm<<<dim3(BWIN*NHEADS, 2), 256>>>();                           // 10
    k_tr_bv<<<dim3(3, 32, 64), dim3(32, 8)>>>();                       // 11
    // attn = (q96·b96 + G) * inq * inb -> second output region
    tc_gemm<4,4><<<dim3(8, 8, BWIN*NHEADS), 256, SMEMSZ>>>(p_q, p_bv, nullptr, attn,
                                                           HDIM, EDIM, EDIM, LTOK,
                                                           0, 0, (long)LTOK*LTOK,
                                                           p_inq, p_inb);       // 12
    // av = attn @ b (N=96 exact) -> g_avt
    tc_gemm<3,3><<<dim3(1, 8, BWIN*NHEADS), 256, SMEMSZ>>>(attn, p_bvt, nullptr, nullptr,
                                                           LTOK, LTOK, LTOK, 0,
                                                           (long)LTOK*LTOK, (long)HDIM*LTOK, 0,
                                                           nullptr, nullptr);   // 13
    // final projection -> first output region
    tc_gemm<2,4><<<dim3(64, 6, 1), 256, SMEMSZ>>>(p_wp, p_avt, projb, out,
                                                  EDIM, EDIM, EDIM, 0, 0, 0, 0,
                                                  nullptr, nullptr);   // 14
}

// round 11
// speedup vs baseline: 1.0679x; 1.0041x over previous
#include <cuda_runtime.h>
#include <math.h>
#include <stdint.h>

// ---------------- problem constants ----------------
#define BATCHN  2
#define EDIM    768
#define LTOK    1024
#define BWIN    8
#define NHEADS  8
#define HDIM    96
#define SZQ     (BWIN*LTOK*EDIM)
#define OUT_ELEMS (BATCHN*EDIM*64*64)

// ---------------- scratch ----------------
__device__ float g_rx [BATCHN*3*1024*1024];
__device__ float g_op [SZQ];
__device__ float g_rp [SZQ];
__device__ float g_lnout[2*SZQ];               // [0]=LN(rp) (q path), [1]=LN(op) (b path)
__device__ float g_qbv [2*SZQ];                // [0]=q, [1]=bv
__device__ float g_avt[BATCHN*4096*EDIM];
__device__ float g_bvt[BWIN*NHEADS*HDIM*LTOK];
__device__ float g_pet[4096*EDIM];
__device__ float g_inq[BWIN*NHEADS*LTOK];
__device__ float g_inb[BWIN*NHEADS*LTOK];
__device__ float g_G  [64];
// tf32-pre-rounded weights
__device__ float g_wqb[2*EDIM*EDIM];           // [0]=qw, [1]=bw
__device__ float g_wp[EDIM*EDIM];
__device__ float g_wr[768*256];
__device__ float g_wo[64*768];                 // origin conv weights transposed [i][oc], fp32

__device__ __forceinline__ uint32_t f2tf32(float f) {
    uint32_t u;
    asm("cvt.rna.tf32.f32 %0, %1;" : "=r"(u) : "f"(f));
    return u;
}
__device__ __forceinline__ float rtf(float f) { return __uint_as_float(f2tf32(f)); }
__device__ __forceinline__ float4 cvt4(float4 v) {
    v.x = rtf(v.x); v.y = rtf(v.y); v.z = rtf(v.z); v.w = rtf(v.w);
    return v;
}

// ---------------- weight pre-rounding + origin-weight transpose ----------------
__global__ void k_cvtw(const float* __restrict__ qw, const float* __restrict__ bw,
                       const float* __restrict__ pw, const float* __restrict__ rw,
                       const float* __restrict__ ow) {
    int i = blockIdx.x * blockDim.x + threadIdx.x;
    if (i < EDIM*EDIM) {
        g_wqb[i]             = rtf(qw[i]);
        g_wqb[EDIM*EDIM + i] = rtf(bw[i]);
        g_wp[i]              = rtf(pw[i]);
    }
    if (i < 768*256) g_wr[i] = rtf(rw[i]);
    if (i < 64*768) {
        int ki = i / 768, oc = i % 768;
        g_wo[i] = ow[oc*64 + ki];
    }
}

// ---------------- bilinear resize 512 -> 1024 ----------------
__global__ void k_resize(const float* __restrict__ x) {
    int idx = blockIdx.x * blockDim.x + threadIdx.x;
    if (idx >= BATCHN*3*1024*1024) return;
    int ox = idx & 1023;
    int oy = (idx >> 10) & 1023;
    int ch = idx >> 20;
    float fy = oy * 0.5f - 0.25f;
    float fx = ox * 0.5f - 0.25f;
    int y0 = (int)floorf(fy); float ty = fy - (float)y0;
    int x0 = (int)floorf(fx); float tx = fx - (float)x0;
    int y1 = y0 + 1, x1 = x0 + 1;
    y0 = max(0, min(511, y0)); y1 = max(0, min(511, y1));
    x0 = max(0, min(511, x0)); x1 = max(0, min(511, x1));
    const float* p = x + (long)ch * 512 * 512;
    float v = p[y0*512+x0]*(1.f-ty)*(1.f-tx) + p[y0*512+x1]*(1.f-ty)*tx
            + p[y1*512+x0]*ty*(1.f-tx)       + p[y1*512+x1]*ty*tx;
    g_rx[idx] = rtf(v);
}

// ---------------- origin conv ----------------
__global__ void k_conv_o(const float* __restrict__ x, const float* __restrict__ bias) {
    __shared__ float patch[16*192];
    int b  = blockIdx.y;
    int y  = blockIdx.x >> 2;
    int xg = blockIdx.x & 3;
    int tid = threadIdx.x;
    for (int e = tid; e < 16*192; e += 768) {
        int p = e / 192, r = e % 192;
        int c = r >> 6, pix = r & 63, py = pix >> 3, px = pix & 7;
        patch[e] = x[(((long)(b*3+c))*512 + y*8+py)*512 + (xg*16+p)*8+px];
    }
    __syncthreads();
    int g = tid >> 8;
    float acc[16];
    float bia = bias[tid];
#pragma unroll
    for (int p = 0; p < 16; p++) acc[p] = bia;
    const float* wt = g_wo + tid;
    const float* pg = patch + g*64;
#pragma unroll 8
    for (int i = 0; i < 64; i++) {
        float wv = wt[i*768];
#pragma unroll
        for (int p = 0; p < 16; p++)
            acc[p] += wv * pg[p*192 + i];
    }
#pragma unroll
    for (int p = 0; p < 16; p++) {
        int xq = xg*16 + p;
        int bwn = (b*2 + (y>>5))*2 + (xq>>5);
        int t   = (y&31)*32 + (xq&31);
        g_op[((long)(bwn*LTOK + t))*EDIM + tid] = acc[p];
    }
}

// ---------------- LayerNorm (both paths) ----------------
__global__ void k_ln(const float* __restrict__ g0, const float* __restrict__ b0,
                     const float* __restrict__ g1, const float* __restrict__ b1) {
    long row = blockIdx.x;
    const float* in = blockIdx.y ? g_rp : g_op;
    const float* gg = blockIdx.y ? g1 : g0;
    const float* bb = blockIdx.y ? b1 : b0;
    // z-order of merged GEMM: z=0 uses LN(rp) (q path), z=1 uses LN(op)
    float* out = blockIdx.y ? g_lnout : (g_lnout + SZQ);
    const float* r = in + row * EDIM;
    float v[3], s = 0.f, ss = 0.f;
#pragma unroll
    for (int j = 0; j < 3; j++) {
        float xv = r[threadIdx.x + j*256];
        v[j] = xv; s += xv; ss += xv*xv;
    }
    __shared__ float shs[8], shss[8];
    for (int o = 16; o; o >>= 1) {
        s  += __shfl_down_sync(0xffffffffu, s,  o);
        ss += __shfl_down_sync(0xffffffffu, ss, o);
    }
    if ((threadIdx.x & 31) == 0) { shs[threadIdx.x>>5] = s; shss[threadIdx.x>>5] = ss; }
    __syncthreads();
    if (threadIdx.x < 8) {
        s = shs[threadIdx.x]; ss = shss[threadIdx.x];
        for (int o = 4; o; o >>= 1) {
            s  += __shfl_down_sync(0xffu, s,  o);
            ss += __shfl_down_sync(0xffu, ss, o);
        }
        if (threadIdx.x == 0) { shs[0] = s; shss[0] = ss; }
    }
    __syncthreads();
    float mu  = shs[0] * (1.f/768.f);
    float var = shss[0] * (1.f/768.f) - mu*mu;
    float rin = rsqrtf(var + 1e-5f);
#pragma unroll
    for (int j = 0; j < 3; j++) {
        int c = threadIdx.x + j*256;
        out[row*EDIM + c] = rtf((v[j]-mu)*rin*gg[c] + bb[c]);
    }
}

// ---------------- RoPE delta table ----------------
__global__ void k_gtab() {
    int tid = threadIdx.x;
    if (tid < 63) {
        float d = (float)(tid - 31);
        float s = 0.f;
#pragma unroll
        for (int f = 0; f < 16; f++)
            s += cosf(d * powf(10.0f, -(float)f / 16.0f));
        g_G[tid] = s;
    }
}

// ---------------- per-row inverse norms ----------------
__global__ void k_norm() {
    int z = blockIdx.x;
    int bwn = z >> 3, h = z & 7;
    const float* src = blockIdx.y ? (g_qbv + SZQ) : g_qbv;
    float* dst       = blockIdx.y ? g_inb : g_inq;
    int wid = threadIdx.x >> 5, lane = threadIdx.x & 31;
    for (int t = wid; t < LTOK; t += 8) {
        const float* r = src + ((long)(bwn*LTOK + t))*EDIM + h*HDIM;
        float s = 0.f;
#pragma unroll
        for (int j = 0; j < 3; j++) {
            float v = r[lane + 32*j];
            s += v*v;
        }
        for (int o = 16; o; o >>= 1) s += __shfl_down_sync(0xffffffffu, s, o);
        if (lane == 0) dst[z*LTOK + t] = rsqrtf(s + 32.0f);
    }
}

// ---------------- transpose b per (bwn,h): [t][d] -> [d][t] ----------------
__global__ void k_tr_bv() {
    __shared__ float s[32][33];
    int z = blockIdx.z; int bwn = z >> 3, h = z & 7;
    int d0 = blockIdx.x * 32, t0 = blockIdx.y * 32;
    int tx = threadIdx.x, ty = threadIdx.y;
#pragma unroll
    for (int j = 0; j < 4; j++) {
        int t = t0 + ty*4 + j;
        s[ty*4+j][tx] = g_qbv[SZQ + ((long)(bwn*LTOK + t))*EDIM + h*HDIM + d0 + tx];
    }
    __syncthreads();
#pragma unroll
    for (int j = 0; j < 4; j++) {
        int d = d0 + ty*4 + j;
        g_bvt[((long)(z*HDIM + d))*LTOK + t0 + tx] = s[tx][ty*4+j];
    }
}

// ---------------- transpose pos_embed: [c][pos] -> [pos][c] ----------------
__global__ void k_tr_pe(const float* __restrict__ pe) {
    __shared__ float s[32][33];
    int c0 = blockIdx.x * 32, p0 = blockIdx.y * 32;
    int tx = threadIdx.x, ty = threadIdx.y;
#pragma unroll
    for (int j = 0; j < 4; j++)
        s[ty*4+j][tx] = pe[(long)(c0 + ty*4 + j)*4096 + p0 + tx];
    __syncthreads();
#pragma unroll
    for (int j = 0; j < 4; j++)
        g_pet[(long)(p0 + ty*4 + j)*EDIM + c0 + tx] = s[tx][ty*4+j];
}

// ================= tf32 mma.sync GEMM (NT), cp.async pipeline + ldmatrix frags =========
#define LDK    36
#define TB     (128*LDK)
#define STAGES 3
#define SMEMSZ ((2*STAGES*TB + 64)*4)

__device__ __forceinline__ void cpa16(uint32_t d, const void* s) {
    asm volatile("cp.async.cg.shared.global [%0], [%1], 16;" :: "r"(d), "l"(s));
}
#define CP_COMMIT() asm volatile("cp.async.commit_group;" ::: "memory")
#define CP_WAIT1()  asm volatile("cp.async.wait_group 1;" ::: "memory")

__device__ __forceinline__ void mma8(float* d, const uint32_t* a, const uint32_t* b) {
    asm volatile(
        "mma.sync.aligned.m16n8k8.row.col.f32.tf32.tf32.f32 "
        "{%0,%1,%2,%3}, {%4,%5,%6,%7}, {%8,%9}, {%0,%1,%2,%3};"
        : "+f"(d[0]), "+f"(d[1]), "+f"(d[2]), "+f"(d[3])
        : "r"(a[0]), "r"(a[1]), "r"(a[2]), "r"(a[3]), "r"(b[0]), "r"(b[1]));
}
__device__ __forceinline__ void ldsm4(uint32_t* r, uint32_t addr) {
    asm volatile("ldmatrix.sync.aligned.m8n8.x4.shared.b16 {%0,%1,%2,%3}, [%4];"
        : "=r"(r[0]), "=r"(r[1]), "=r"(r[2]), "=r"(r[3]) : "r"(addr));
}
__device__ __forceinline__ void ldsm2(uint32_t* r, uint32_t addr) {
    asm volatile("ldmatrix.sync.aligned.m8n8.x2.shared.b16 {%0,%1}, [%2];"
        : "=r"(r[0]), "=r"(r[1]) : "r"(addr));
}

template<int EPI, int NMMA>
__global__ __launch_bounds__(256)
void tc_gemm(const float* __restrict__ A, const float* __restrict__ B,
             const float* __restrict__ bias, float* __restrict__ C,
             int K, int lda, int ldb, int ldc,
             long sA, long sB, long sC,
             const float* __restrict__ sr, const float* __restrict__ sc) {
    extern __shared__ __align__(16) float sm[];
    uint32_t sbase = (uint32_t)__cvta_generic_to_shared(sm);
    int tid = threadIdx.x;
    int wid = tid >> 5, lane = tid & 31;
    int tg = lane >> 2, t4 = lane & 3;
    long z = blockIdx.z;
    if (EPI == 4) {
        long off = (z >> 3) * (long)LTOK * EDIM + (z & 7) * HDIM;
        A += off; B += off;
        C += z * sC;
    } else {
        A += z * sA;
        if (EPI == 1) B += (z % 3) * 65536; else B += z * sB;
        if (EPI == 0) {
            C += z * sC;
            if (z != 0 && sr) bias = sr;     // second bias for merged z=2 launch
        }
    }

    int row0 = blockIdx.y * 128, col0 = blockIdx.x * (32*NMMA);
    int wm = wid >> 2, wn = wid & 3;
    int m_base = wm * 64, n_base = wn * (8*NMMA);

    float acc[4][NMMA][4] = {};
    const int KT = K >> 5;

    int am[4], ac[4];
#pragma unroll
    for (int p = 0; p < 4; p++) {
        int i2 = tid + p*256;
        am[p] = i2 >> 3;
        ac[p] = (i2 & 7) << 2;
    }

    // ldmatrix per-thread base offsets (bytes, relative to stage base)
    int quad = lane >> 3, l8 = lane & 7;
    uint32_t aoffB = (uint32_t)(((m_base + l8 + ((quad & 1) << 3))*LDK + ((quad >> 1) << 2)) * 4);
    int bl = lane & 15;
    uint32_t boffB = (uint32_t)((TB + (n_base + (bl & 7))*LDK + ((bl >> 3) << 2)) * 4);
    // paired B x4: groups 0..3 -> (row n_base + (g>>1)*8 + l8, koff (g&1)*4)
    uint32_t boffB4 = (uint32_t)((TB + (n_base + ((lane >> 4) << 3) + l8)*LDK
                                  + (((lane >> 3) & 1) << 2)) * 4);

    auto fill = [&](int kt) {
        int stg = kt % STAGES;
        int k0 = kt << 5;
        uint32_t ab = sbase + (uint32_t)(stg * (2*TB)) * 4u;
        uint32_t bb = ab + TB*4u;
#pragma unroll
        for (int p = 0; p < 4; p++) {
            const float* srcA;
            if (EPI == 1) {
                int pos = row0 + am[p];
                int y = pos >> 6, xq = pos & 63;
                int k = k0 + ac[p];
                int py = k >> 4, px = k & 15;
                srcA = g_rx + ((long)z*1024 + y*16 + py)*1024 + xq*16 + px;
            } else {
                srcA = A + (long)(row0 + am[p])*lda + k0 + ac[p];
            }
            cpa16(ab + (uint32_t)(am[p]*LDK + ac[p])*4u, srcA);
        }
#pragma unroll
        for (int p = 0; p < NMMA; p++)
            cpa16(bb + (uint32_t)(am[p]*LDK + ac[p])*4u,
                  B + (long)(col0 + am[p])*ldb + k0 + ac[p]);
    };

    fill(0); CP_COMMIT();
    fill(1); CP_COMMIT();

    for (int kt = 0; kt < KT; kt++) {
        CP_WAIT1();
        __syncthreads();
        if (kt + 2 < KT) fill(kt + 2);
        CP_COMMIT();
        uint32_t stgoff = sbase + (uint32_t)((kt % STAGES) * (2*TB)) * 4u;
#pragma unroll
        for (int ks = 0; ks < 4; ks++) {
            uint32_t af[4][4], bf[NMMA][2];
#pragma unroll
            for (int im = 0; im < 4; im++)
                ldsm4(af[im], stgoff + aoffB + (uint32_t)((im*16*LDK + ks*8)*4));
            if (NMMA == 4) {
                ldsm4(&bf[0][0], stgoff + boffB4 + (uint32_t)((ks*8)*4));
                ldsm4(&bf[2][0], stgoff + boffB4 + (uint32_t)((16*LDK + ks*8)*4));
            } else {
                ldsm4(&bf[0][0], stgoff + boffB4 + (uint32_t)((ks*8)*4));
                ldsm2(&bf[2][0], stgoff + boffB  + (uint32_t)((2*8*LDK + ks*8)*4));
            }
#pragma unroll
            for (int im = 0; im < 4; im++)
#pragma unroll
                for (int in = 0; in < NMMA; in++)
                    mma8(acc[im][in], af[im], bf[in]);
        }
    }

    __syncthreads();
    if (EPI == 4 && tid < 63) sm[2*STAGES*TB + tid] = g_G[tid];
#pragma unroll
    for (int im = 0; im < 4; im++) {
#pragma unroll
        for (int in = 0; in < NMMA; in++) {
            int r = m_base + im*16 + tg;
            int c = n_base + in*8 + t4*2;
            int s0 = ((c >> 2) ^ (r & 31));
            float* p0 = sm + (r << 7) + (s0 << 2) + (c & 3);
            p0[0] = acc[im][in][0]; p0[1] = acc[im][in][1];
            int r2 = r + 8;
            int s2 = ((c >> 2) ^ (r2 & 31));
            float* p2 = sm + (r2 << 7) + (s2 << 2) + (c & 3);
            p2[0] = acc[im][in][2]; p2[1] = acc[im][in][3];
        }
    }
    __syncthreads();

#pragma unroll 1
    for (int pass = 0; pass < 16; pass++) {
        int r  = pass*8 + wid;
        int c4 = lane;
        if (NMMA == 3 && c4 >= 24) continue;
        int slot = c4 ^ (r & 31);
        float4 v = *(const float4*)(sm + (r << 7) + (slot << 2));
        int row = row0 + r;
        int col = col0 + (c4 << 2);
        if (EPI == 0) {
            if (bias) { v.x += bias[col]; v.y += bias[col+1]; v.z += bias[col+2]; v.w += bias[col+3]; }
            *(float4*)(C + (long)row*ldc + col) = cvt4(v);
        } else if (EPI == 1) {
            int pos = row;
            int y = pos >> 6, xq = pos & 63;
            int bb_ = (int)(z / 3), g = (int)(z % 3);
            int bwn = (bb_*2 + (y>>5))*2 + (xq>>5);
            int t   = (y&31)*32 + (xq&31);
            int cc  = g*256 + col;
            float4 pb4 = *(const float4*)(g_pet + (long)pos*EDIM + cc);
            v.x += bias[cc+0] + pb4.x; v.y += bias[cc+1] + pb4.y;
            v.z += bias[cc+2] + pb4.z; v.w += bias[cc+3] + pb4.w;
            *(float4*)(g_rp + ((long)(bwn*LTOK + t))*EDIM + cc) = v;
        } else if (EPI == 2) {
            int oc = row, tok = col;
            int bb_ = tok >> 12, p = tok & 4095;
            float bia = bias[oc];
            v.x += bia; v.y += bia; v.z += bia; v.w += bia;
            *(float4*)(C + (long)bb_*(EDIM*4096) + (long)oc*4096 + p) = v;
        } else if (EPI == 3) {
            int bwn = (int)(z >> 3), h = (int)(z & 7);
            int t = row;
            int b_ = bwn >> 2, wy = (bwn >> 1) & 1, wx = bwn & 1;
            int ly = t >> 5, lx = t & 31;
            int tok = b_*4096 + (wy*32 + ly)*64 + (wx*32 + lx);
            *(float4*)(g_avt + (long)tok*EDIM + h*HDIM + (c4 << 2)) = cvt4(v);
        } else { // EPI 4
            const float* smG = sm + 2*STAGES*TB;
            int xi = row & 31, yi = row >> 5;
            float iq = sr[z*LTOK + row];
            float4 ib4 = *(const float4*)(sc + z*LTOK + col);
            int xj0 = col & 31, yj0 = col >> 5;
            v.x = (v.x + smG[xi - xj0     + 31] + smG[yi - yj0 + 31]) * iq * ib4.x;
            v.y = (v.y + smG[xi - (xj0+1) + 31] + smG[yi - yj0 + 31]) * iq * ib4.y;
            v.z = (v.z + smG[xi - (xj0+2) + 31] + smG[yi - yj0 + 31]) * iq * ib4.z;
            v.w = (v.w + smG[xi - (xj0+3) + 31] + smG[yi - yj0 + 31]) * iq * ib4.w;
            *(float4*)(C + (long)row*ldc + col) = cvt4(v);
        }
    }
}

// ---------------- host launch ----------------
static float* sym_addr(const void* sym) {
    void* p = nullptr;
    cudaGetSymbolAddress(&p, sym);
    return (float*)p;
}

extern "C" void kernel_launch(void* const* d_in, const int* in_sizes, int n_in,
                              void* d_out, int out_size) {
    const float* x      = (const float*)d_in[0];
    const float* ow     = (const float*)d_in[1];
    const float* obias  = (const float*)d_in[2];
    const float* rw     = (const float*)d_in[3];
    const float* rbias  = (const float*)d_in[4];
    const float* pe     = (const float*)d_in[5];
    const float* nb_g   = (const float*)d_in[6];
    const float* nb_b   = (const float*)d_in[7];
    const float* nq_g   = (const float*)d_in[8];
    const float* nq_b   = (const float*)d_in[9];
    const float* qw     = (const float*)d_in[10];
    const float* qb     = (const float*)d_in[11];
    const float* bw     = (const float*)d_in[12];
    const float* bb     = (const float*)d_in[13];
    const float* projw  = (const float*)d_in[14];
    const float* projb  = (const float*)d_in[15];

    float* out  = (float*)d_out;
    float* attn = out + OUT_ELEMS;

    float* p_rx    = sym_addr(g_rx);
    float* p_lnout = sym_addr(g_lnout);
    float* p_qbv   = sym_addr(g_qbv);
    float* p_avt   = sym_addr(g_avt);
    float* p_bvt   = sym_addr(g_bvt);
    float* p_inq   = sym_addr(g_inq);
    float* p_inb   = sym_addr(g_inb);
    float* p_wqb   = sym_addr(g_wqb);
    float* p_wp    = sym_addr(g_wp);
    float* p_wr    = sym_addr(g_wr);

    cudaFuncSetAttribute(tc_gemm<0,4>, cudaFuncAttributeMaxDynamicSharedMemorySize, SMEMSZ);
    cudaFuncSetAttribute(tc_gemm<1,4>, cudaFuncAttributeMaxDynamicSharedMemorySize, SMEMSZ);
    cudaFuncSetAttribute(tc_gemm<2,4>, cudaFuncAttributeMaxDynamicSharedMemorySize, SMEMSZ);
    cudaFuncSetAttribute(tc_gemm<3,3>, cudaFuncAttributeMaxDynamicSharedMemorySize, SMEMSZ);
    cudaFuncSetAttribute(tc_gemm<4,4>, cudaFuncAttributeMaxDynamicSharedMemorySize, SMEMSZ);

    k_cvtw<<<2304, 256>>>(qw, bw, projw, rw, ow);                      // 1
    k_resize<<<24576, 256>>>(x);                                       // 2
    k_tr_pe<<<dim3(24, 128), dim3(32, 8)>>>(pe);                       // 3
    // resize conv as tf32 GEMM with fused im2col gather
    tc_gemm<1,4><<<dim3(2, 32, 6), 256, SMEMSZ>>>(p_rx, p_wr, rbias, nullptr,
                                                  256, 256, 256, 0,
                                                  0, 0, 0, nullptr, nullptr);   // 4
    k_conv_o<<<dim3(256, BATCHN), 768>>>(x, obias);                    // 5
    k_ln<<<dim3(BWIN*LTOK, 2), 256>>>(nb_g, nb_b, nq_g, nq_b);         // 6
    // merged q+b projections: z=0 (LN(rp), qw, qb)->q ; z=1 (LN(op), bw, bb)->bv
    tc_gemm<0,4><<<dim3(6, 64, 2), 256, SMEMSZ>>>(p_lnout, p_wqb, qb, p_qbv,
                                                  EDIM, EDIM, EDIM, EDIM,
                                                  (long)SZQ, (long)EDIM*EDIM, (long)SZQ,
                                                  bb, nullptr);        // 7
    k_gtab<<<1, 64>>>();                                               // 8
    k_norm<<<dim3(BWIN*NHEADS, 2), 256>>>();                           // 9
    k_tr_bv<<<dim3(3, 32, 64), dim3(32, 8)>>>();                       // 10
    // attn = (q96·b96 + G) * inq * inb -> second output region
    tc_gemm<4,4><<<dim3(8, 8, BWIN*NHEADS), 256, SMEMSZ>>>(p_qbv, p_qbv + SZQ, nullptr, attn,
                                                           HDIM, EDIM, EDIM, LTOK,
                                                           0, 0, (long)LTOK*LTOK,
                                                           p_inq, p_inb);       // 11
    // av = attn @ b (N=96 exact) -> g_avt
    tc_gemm<3,3><<<dim3(1, 8, BWIN*NHEADS), 256, SMEMSZ>>>(attn, p_bvt, nullptr, nullptr,
                                                           LTOK, LTOK, LTOK, 0,
                                                           (long)LTOK*LTOK, (long)HDIM*LTOK, 0,
                                                           nullptr, nullptr);   // 12
    // final projection -> first output region
    tc_gemm<2,4><<<dim3(64, 6, 1), 256, SMEMSZ>>>(p_wp, p_avt, projb, out,
                                                  EDIM, EDIM, EDIM, 0, 0, 0, 0,
                                                  nullptr, nullptr);   // 13
}